// round 3
// baseline (speedup 1.0000x reference)
#include <cuda_runtime.h>
#include <math.h>

#define NTOK 16384
#define DDIM 256
#define KCB  512
#define LLV  8
#define BATCH 16

// ---------------- device scratch (static, no allocations) ----------------
__device__ float g_S[NTOK * KCB];      // raw dot[n,k] for current level (32 MB)
__device__ float g_rss[NTOK];          // ||fl(z-g)||^2 per token (order-free)
__device__ float g_g[DDIM];            // global_sum, fp32, reference-exact chain
__device__ float g_wss[LLV * KCB];     // ||W_k||^2
__device__ float g_normW[LLV * KCB];   // ||W_k||
__device__ float g_kl[NTOK];           // kl accumulator
__device__ int   g_idx[NTOK * LLV];    // picks
__device__ float g_ltok[NTOK];         // per-token loss

// ---------------- init: wss, norms, zero state ----------------
__global__ void k_init(const float* __restrict__ W) {
    int gid = blockIdx.x * blockDim.x + threadIdx.x;   // 64*256 = 16384
    if (gid < LLV * KCB) {
        const float4* row = (const float4*)(W + (size_t)gid * DDIM);
        float acc = 0.f;
        #pragma unroll 8
        for (int j = 0; j < DDIM / 4; j++) {
            float4 w4 = row[j];
            acc = __fadd_rn(acc, __fmul_rn(w4.x, w4.x));
            acc = __fadd_rn(acc, __fmul_rn(w4.y, w4.y));
            acc = __fadd_rn(acc, __fmul_rn(w4.z, w4.z));
            acc = __fadd_rn(acc, __fmul_rn(w4.w, w4.w));
        }
        g_wss[gid]   = acc;
        g_normW[gid] = sqrtf(acc);
    }
    if (gid < NTOK) g_kl[gid] = 0.f;
    if (gid < DDIM) g_g[gid]  = 0.f;
}

// ---------------- rss[n] = sum_d fl(fl(z-g)^2)  (order-free: only binade matters)
__global__ void k_rss(const float* __restrict__ Z) {
    int tid = threadIdx.x;
    int warp = tid >> 5, lane = tid & 31;
    int n = blockIdx.x * 8 + warp;
    const float* zr = Z + (size_t)n * DDIM;
    float acc = 0.f;
    #pragma unroll
    for (int j = 0; j < 8; j++) {
        int d = lane + j * 32;
        float r = __fsub_rn(zr[d], g_g[d]);
        acc = __fadd_rn(acc, __fmul_rn(r, r));
    }
    #pragma unroll
    for (int o = 16; o; o >>= 1) acc += __shfl_down_sync(0xffffffffu, acc, o);
    if (lane == 0) g_rss[n] = acc;
}

// ---------------- GEMM: dot[n,k] = in-order fused-FMA chain over d of fl(z-g)*W
__global__ __launch_bounds__(256, 2) void k_gemm(const float* __restrict__ Z,
                                                 const float* __restrict__ W) {
    __shared__ float As[8][132];
    __shared__ float Bs[8][132];
    __shared__ float sg[DDIM];
    int tid = threadIdx.x;
    int bx = blockIdx.x, by = blockIdx.y;
    int tx = tid & 15, ty = tid >> 4;
    int lrow = tid >> 1;
    int lc4  = (tid & 1) * 4;
    const float* Ap = Z + (size_t)(by * 128 + lrow) * DDIM + lc4;
    const float* Bp = W + (size_t)(bx * 128 + lrow) * DDIM + lc4;

    sg[tid] = g_g[tid];

    float acc[8][8];
    #pragma unroll
    for (int i = 0; i < 8; i++)
        #pragma unroll
        for (int j = 0; j < 8; j++) acc[i][j] = 0.f;

    float4 a4 = *(const float4*)Ap;
    float4 b4 = *(const float4*)Bp;
    __syncthreads();   // sg visible to all threads

    for (int k0 = 0; k0 < DDIM; k0 += 8) {
        As[lc4 + 0][lrow] = __fsub_rn(a4.x, sg[k0 + lc4 + 0]);
        As[lc4 + 1][lrow] = __fsub_rn(a4.y, sg[k0 + lc4 + 1]);
        As[lc4 + 2][lrow] = __fsub_rn(a4.z, sg[k0 + lc4 + 2]);
        As[lc4 + 3][lrow] = __fsub_rn(a4.w, sg[k0 + lc4 + 3]);
        Bs[lc4 + 0][lrow] = b4.x; Bs[lc4 + 1][lrow] = b4.y;
        Bs[lc4 + 2][lrow] = b4.z; Bs[lc4 + 3][lrow] = b4.w;
        __syncthreads();
        if (k0 + 8 < DDIM) {
            a4 = *(const float4*)(Ap + k0 + 8);
            b4 = *(const float4*)(Bp + k0 + 8);
        }
        #pragma unroll
        for (int kk = 0; kk < 8; kk++) {     // ascending d: in-order FMA chain
            float a[8], b[8];
            *(float4*)&a[0] = *(const float4*)&As[kk][ty * 4];
            *(float4*)&a[4] = *(const float4*)&As[kk][64 + ty * 4];
            *(float4*)&b[0] = *(const float4*)&Bs[kk][tx * 4];
            *(float4*)&b[4] = *(const float4*)&Bs[kk][64 + tx * 4];
            #pragma unroll
            for (int i = 0; i < 8; i++)
                #pragma unroll
                for (int j = 0; j < 8; j++) acc[i][j] = __fmaf_rn(a[i], b[j], acc[i][j]);
        }
        __syncthreads();
    }
    #pragma unroll
    for (int i = 0; i < 8; i++) {
        int r = by * 128 + ((i < 4) ? (ty * 4 + i) : (64 + ty * 4 + i - 4));
        float* dst = g_S + (size_t)r * KCB + bx * 128;
        #pragma unroll
        for (int jh = 0; jh < 2; jh++) {
            int cb = jh ? (64 + tx * 4) : (tx * 4);
            float4 v;
            v.x = acc[i][jh * 4 + 0]; v.y = acc[i][jh * 4 + 1];
            v.z = acc[i][jh * 4 + 2]; v.w = acc[i][jh * 4 + 3];
            *(float4*)(dst + cb) = v;
        }
    }
}

// ---------------- per-token: m_k = fl(fl(rss+wss_k) - 2*dot_k); argmin w/ first-index
// ties (== reference argmax of -m with first-occurrence); KL via log_softmax mimicry.
__global__ void k_reduce(int l) {
    int tid = threadIdx.x;
    int warp = tid >> 5, lane = tid & 31;
    int n = blockIdx.x * 8 + warp;
    const float* dotr = g_S + (size_t)n * KCB;
    const float* wss  = g_wss + l * KCB;
    float rss = g_rss[n];

    float v[16];
    #pragma unroll
    for (int j = 0; j < 16; j++) {
        int k = lane + j * 32;
        float t = __fadd_rn(rss, wss[k]);
        v[j] = __fsub_rn(t, 2.0f * dotr[k]);
    }
    float best = v[0]; int bidx = lane;
    #pragma unroll
    for (int j = 1; j < 16; j++) {
        int k = lane + j * 32;
        if (v[j] < best || (v[j] == best && k < bidx)) { best = v[j]; bidx = k; }
    }
    #pragma unroll
    for (int o = 16; o; o >>= 1) {
        float ob = __shfl_down_sync(0xffffffffu, best, o);
        int   oi = __shfl_down_sync(0xffffffffu, bidx, o);
        if (ob < best || (ob == best && oi < bidx)) { best = ob; bidx = oi; }
    }
    best = __shfl_sync(0xffffffffu, best, 0);   // min m == -max dist
    bidx = __shfl_sync(0xffffffffu, bidx, 0);

    // log_softmax: shifted_k = fl(dist_k - dmax) = fl(best - v_k)
    float esum = 0.f;
    float sh[16];
    #pragma unroll
    for (int j = 0; j < 16; j++) {
        sh[j] = __fsub_rn(best, v[j]);
        esum += expf(sh[j]);
    }
    #pragma unroll
    for (int o = 16; o; o >>= 1) esum += __shfl_down_sync(0xffffffffu, esum, o);
    esum = __shfl_sync(0xffffffffu, esum, 0);
    float L = logf(esum);
    float psum = 0.f;
    #pragma unroll
    for (int j = 0; j < 16; j++) psum += __fsub_rn(sh[j], L);
    #pragma unroll
    for (int o = 16; o; o >>= 1) psum += __shfl_down_sync(0xffffffffu, psum, o);

    if (lane == 0) {
        float mean = psum * (1.0f / 512.0f);                 // exact pow2 scale
        float kl = __fsub_rn(-6.238324625039508f, mean);     // -log(512) - mean
        g_kl[n] = __fadd_rn(g_kl[n], __fmul_rn(kl, 0.1f));
        g_idx[n * LLV + l] = bidx;
    }
}

// ---------------- g update: strictly sequential in-order fp32 chain over n
__global__ void k_gchain(const float* __restrict__ W, int l) {
    __shared__ int sidx[256];
    int d = threadIdx.x;
    const float* Wl = W + (size_t)l * KCB * DDIM;
    float part = 0.f;
    for (int n0 = 0; n0 < NTOK; n0 += 256) {
        sidx[d] = g_idx[(n0 + d) * LLV + l];
        __syncthreads();
        #pragma unroll 8
        for (int j = 0; j < 256; j++)
            part = __fadd_rn(part, Wl[(size_t)sidx[j] * DDIM + d]);
        __syncthreads();
    }
    g_g[d] = __fadd_rn(g_g[d], part);
}

// ---------------- q_out (transposed write) + per-token loss ----------------
__global__ void k_final_q(const float* __restrict__ W, float* __restrict__ out,
                          long long o_q) {
    __shared__ int   sidx[32][8];
    __shared__ float sq[32][257];
    int tid = threadIdx.x;
    int tbase = blockIdx.x * 32;
    sidx[tid >> 3][tid & 7] = g_idx[(tbase + (tid >> 3)) * LLV + (tid & 7)];
    __syncthreads();

    int d = tid;
    for (int t = 0; t < 32; t++) {
        float acc = 0.f;
        #pragma unroll
        for (int l = 0; l < LLV; l++)   // in-order over levels
            acc = __fadd_rn(acc, W[(size_t)(l * KCB + sidx[t][l]) * DDIM + d]);
        sq[t][d] = acc;
    }
    if (tid < 32) {
        int n = tbase + tid;
        float nl = 0.f;
        float un = g_normW[sidx[tid][0]];
        #pragma unroll
        for (int l = 0; l < 7; l++) {
            float lo = g_normW[(l + 1) * KCB + sidx[tid][l + 1]];
            float r  = fmaxf(__fmul_rn(__fdiv_rn(lo, un), 4.0f), 1.0f) - 1.0f;
            nl = __fadd_rn(nl, __fmul_rn(r, r));
            un = lo;
        }
        float nlm = __fdiv_rn(nl, 7.0f);
        g_ltok[n] = __fadd_rn(g_kl[n], __fmul_rn(nlm, 0.1f));
    }
    __syncthreads();
    if (o_q >= 0) {
        int b   = tbase >> 10;
        int hw0 = tbase & 1023;
        float* dst = out + o_q + (size_t)b * (DDIM * 1024);
        for (int it = 0; it < 32; it++) {
            int e = it * 256 + tid;
            int t = e & 31;
            int dd = e >> 5;
            dst[(size_t)dd * 1024 + hw0 + t] = sq[t][dd];
        }
    }
}

// ---------------- per-batch loss mean (in-order chain, /1024 exact) ----------------
__global__ void k_final_loss(float* __restrict__ out, long long o_l) {
    int b = blockIdx.x;
    if (threadIdx.x == 0 && o_l >= 0) {
        float s = 0.f;
        for (int i = 0; i < 1024; i++) s = __fadd_rn(s, g_ltok[b * 1024 + i]);
        out[o_l + b] = s * (1.0f / 1024.0f);
    }
}

// ---------------- indices (as float) + one-hot probs scatter ----------------
__global__ void k_final_scatter(float* __restrict__ out, long long o_i, long long o_p) {
    int gid = blockIdx.x * blockDim.x + threadIdx.x;
    if (gid >= NTOK * LLV) return;
    int iv = g_idx[gid];
    if (o_i >= 0) out[o_i + gid] = (float)iv;
    if (o_p >= 0) out[o_p + (size_t)gid * KCB + iv] = 1.0f;
}

// ---------------- launch ----------------
extern "C" void kernel_launch(void* const* d_in, const int* in_sizes, int n_in,
                              void* d_out, int out_size) {
    const float* z = nullptr;
    const float* w = nullptr;
    for (int i = 0; i < n_in; i++) {
        if (in_sizes[i] == NTOK * DDIM)            z = (const float*)d_in[i];
        else if (in_sizes[i] == LLV * KCB * DDIM)  w = (const float*)d_in[i];
    }
    float* out = (float*)d_out;

    const long long SZ_Q = (long long)BATCH * DDIM * 1024;   // 4194304
    const long long SZ_I = (long long)NTOK * LLV;            // 131072
    const long long SZ_L = BATCH;                            // 16
    const long long SZ_P = (long long)NTOK * LLV * KCB;      // 67108864
    long long o_q = 0, o_i = -1, o_l = -1, o_p = -1;
    long long total = SZ_Q + SZ_I + SZ_L + SZ_P;
    if ((long long)out_size >= total) { o_i = SZ_Q; o_l = o_i + SZ_I; o_p = o_l + SZ_L; }

    cudaMemsetAsync(d_out, 0, (size_t)out_size * sizeof(float), 0);
    k_init<<<64, 256>>>(w);
    for (int l = 0; l < LLV; l++) {
        k_rss<<<2048, 256>>>(z);
        k_gemm<<<dim3(4, 128), 256>>>(z, w + (size_t)l * KCB * DDIM);
        k_reduce<<<2048, 256>>>(l);
        k_gchain<<<1, 256>>>(w, l);
    }
    k_final_q<<<512, 256>>>(w, out, o_q);
    k_final_loss<<<BATCH, 256>>>(out, o_l);
    k_final_scatter<<<512, 256>>>(out, o_i, o_p);
}

// round 4
// speedup vs baseline: 1.2670x; 1.2670x over previous
#include <cuda_runtime.h>
#include <math.h>

#define NTOK 16384
#define DDIM 256
#define KCB  512
#define LLV  8
#define BATCH 16

// ---------------- device scratch (static, no allocations) ----------------
__device__ float g_S[NTOK * KCB];      // raw dot[n,k] for current level (32 MB)
__device__ float g_rss[NTOK];          // ||fl(z-g)||^2 per token
__device__ float g_g[DDIM];            // global_sum, fp32, reference-exact chain
__device__ float g_wss[LLV * KCB];     // ||W_k||^2
__device__ float g_normW[LLV * KCB];   // ||W_k||
__device__ float g_kl[NTOK];           // kl accumulator
__device__ int   g_idx[NTOK * LLV];    // picks
__device__ float g_ltok[NTOK];         // per-token loss

// ---------------- packed f32x2 helpers (bitwise == two scalar fp32 ops) ----------------
__device__ __forceinline__ unsigned long long pk2(float lo, float hi) {
    unsigned long long r;
    asm("mov.b64 %0, {%1, %2};" : "=l"(r) : "f"(lo), "f"(hi));
    return r;
}
__device__ __forceinline__ void upk2(unsigned long long v, float& lo, float& hi) {
    asm("mov.b64 {%0, %1}, %2;" : "=f"(lo), "=f"(hi) : "l"(v));
}
__device__ __forceinline__ unsigned long long ffma2(unsigned long long a,
                                                    unsigned long long b,
                                                    unsigned long long c) {
    unsigned long long d;
    asm("fma.rn.f32x2 %0, %1, %2, %3;" : "=l"(d) : "l"(a), "l"(b), "l"(c));
    return d;
}

// ---------------- init: wss, norms, zero state ----------------
__global__ void k_init(const float* __restrict__ W) {
    int gid = blockIdx.x * blockDim.x + threadIdx.x;   // 64*256 = 16384
    if (gid < LLV * KCB) {
        const float4* row = (const float4*)(W + (size_t)gid * DDIM);
        float acc = 0.f;
        #pragma unroll 8
        for (int j = 0; j < DDIM / 4; j++) {
            float4 w4 = row[j];
            acc = __fadd_rn(acc, __fmul_rn(w4.x, w4.x));
            acc = __fadd_rn(acc, __fmul_rn(w4.y, w4.y));
            acc = __fadd_rn(acc, __fmul_rn(w4.z, w4.z));
            acc = __fadd_rn(acc, __fmul_rn(w4.w, w4.w));
        }
        g_wss[gid]   = acc;
        g_normW[gid] = sqrtf(acc);
    }
    if (gid < NTOK) g_kl[gid] = 0.f;
    if (gid < DDIM) g_g[gid]  = 0.f;
}

// ---------------- rss[n] = sum_d fl(fl(z-g)^2) ----------------
__global__ void k_rss(const float* __restrict__ Z) {
    int tid = threadIdx.x;
    int warp = tid >> 5, lane = tid & 31;
    int n = blockIdx.x * 8 + warp;
    const float4* zr = (const float4*)(Z + (size_t)n * DDIM);
    const float4* gr = (const float4*)g_g;
    float acc = 0.f;
    #pragma unroll
    for (int j = 0; j < 2; j++) {
        int f = lane + j * 32;
        float4 z4 = zr[f];
        float4 g4 = gr[f];
        float r;
        r = __fsub_rn(z4.x, g4.x); acc = __fadd_rn(acc, __fmul_rn(r, r));
        r = __fsub_rn(z4.y, g4.y); acc = __fadd_rn(acc, __fmul_rn(r, r));
        r = __fsub_rn(z4.z, g4.z); acc = __fadd_rn(acc, __fmul_rn(r, r));
        r = __fsub_rn(z4.w, g4.w); acc = __fadd_rn(acc, __fmul_rn(r, r));
    }
    #pragma unroll
    for (int o = 16; o; o >>= 1) acc += __shfl_down_sync(0xffffffffu, acc, o);
    if (lane == 0) g_rss[n] = acc;
}

// ---------------- GEMM: dot[n,k] = in-order FMA chain over d of fl(z-g)*W ----------
// 128x128 tile, BK=8, 8x8/thread via f32x2 (row-paired accumulators), double-buffered.
__global__ __launch_bounds__(256, 2) void k_gemm(const float* __restrict__ Z,
                                                 const float* __restrict__ W) {
    __shared__ float As[2][8][132];
    __shared__ float Bs[2][8][132];
    __shared__ float sg[DDIM];
    int tid = threadIdx.x;
    int bx = blockIdx.x, by = blockIdx.y;
    int tx = tid & 15, ty = tid >> 4;
    int ty4 = ty * 4, tx4 = tx * 4;
    int lrow = tid >> 1;
    int lc4  = (tid & 1) * 4;
    const float* Ap = Z + (size_t)(by * 128 + lrow) * DDIM + lc4;
    const float* Bp = W + (size_t)(bx * 128 + lrow) * DDIM + lc4;

    sg[tid] = g_g[tid];

    unsigned long long acc2[4][8];   // row-pairs x 8 cols
    #pragma unroll
    for (int p = 0; p < 4; p++)
        #pragma unroll
        for (int j = 0; j < 8; j++) acc2[p][j] = 0ull;

    float4 a4 = *(const float4*)Ap;          // tile 0
    float4 b4 = *(const float4*)Bp;
    __syncthreads();                          // sg visible

    // store tile 0 into buf 0
    As[0][lc4 + 0][lrow] = __fsub_rn(a4.x, sg[lc4 + 0]);
    As[0][lc4 + 1][lrow] = __fsub_rn(a4.y, sg[lc4 + 1]);
    As[0][lc4 + 2][lrow] = __fsub_rn(a4.z, sg[lc4 + 2]);
    As[0][lc4 + 3][lrow] = __fsub_rn(a4.w, sg[lc4 + 3]);
    Bs[0][lc4 + 0][lrow] = b4.x; Bs[0][lc4 + 1][lrow] = b4.y;
    Bs[0][lc4 + 2][lrow] = b4.z; Bs[0][lc4 + 3][lrow] = b4.w;
    a4 = *(const float4*)(Ap + 8);           // prefetch tile 1
    b4 = *(const float4*)(Bp + 8);
    __syncthreads();

    for (int t = 0; t < 32; t++) {
        int buf = t & 1;
        if (t + 1 < 32) {
            int nb = (t + 1) & 1;
            int k1 = (t + 1) * 8;
            As[nb][lc4 + 0][lrow] = __fsub_rn(a4.x, sg[k1 + lc4 + 0]);
            As[nb][lc4 + 1][lrow] = __fsub_rn(a4.y, sg[k1 + lc4 + 1]);
            As[nb][lc4 + 2][lrow] = __fsub_rn(a4.z, sg[k1 + lc4 + 2]);
            As[nb][lc4 + 3][lrow] = __fsub_rn(a4.w, sg[k1 + lc4 + 3]);
            Bs[nb][lc4 + 0][lrow] = b4.x; Bs[nb][lc4 + 1][lrow] = b4.y;
            Bs[nb][lc4 + 2][lrow] = b4.z; Bs[nb][lc4 + 3][lrow] = b4.w;
            if (t + 2 < 32) {
                a4 = *(const float4*)(Ap + (t + 2) * 8);
                b4 = *(const float4*)(Bp + (t + 2) * 8);
            }
        }
        #pragma unroll
        for (int kk = 0; kk < 8; kk++) {     // ascending d: in-order FMA chain
            // row pairs straight from shared (no packing needed)
            unsigned long long a01 = *(const unsigned long long*)&As[buf][kk][ty4];
            unsigned long long a23 = *(const unsigned long long*)&As[buf][kk][ty4 + 2];
            unsigned long long a45 = *(const unsigned long long*)&As[buf][kk][64 + ty4];
            unsigned long long a67 = *(const unsigned long long*)&As[buf][kk][64 + ty4 + 2];
            float4 bl = *(const float4*)&Bs[buf][kk][tx4];
            float4 bh = *(const float4*)&Bs[buf][kk][64 + tx4];
            unsigned long long bb[8];
            bb[0] = pk2(bl.x, bl.x); bb[1] = pk2(bl.y, bl.y);
            bb[2] = pk2(bl.z, bl.z); bb[3] = pk2(bl.w, bl.w);
            bb[4] = pk2(bh.x, bh.x); bb[5] = pk2(bh.y, bh.y);
            bb[6] = pk2(bh.z, bh.z); bb[7] = pk2(bh.w, bh.w);
            #pragma unroll
            for (int j = 0; j < 8; j++) {
                acc2[0][j] = ffma2(a01, bb[j], acc2[0][j]);
                acc2[1][j] = ffma2(a23, bb[j], acc2[1][j]);
                acc2[2][j] = ffma2(a45, bb[j], acc2[2][j]);
                acc2[3][j] = ffma2(a67, bb[j], acc2[3][j]);
            }
        }
        __syncthreads();
    }

    // epilogue: unpack row pairs, store raw dots
    #pragma unroll
    for (int p = 0; p < 4; p++) {
        int rbase = (p < 2) ? (ty4 + p * 2) : (64 + ty4 + (p - 2) * 2);
        float lo[8], hi[8];
        #pragma unroll
        for (int j = 0; j < 8; j++) upk2(acc2[p][j], lo[j], hi[j]);
        #pragma unroll
        for (int h = 0; h < 2; h++) {
            int r = by * 128 + rbase + h;
            const float* src = h ? hi : lo;
            float* dst = g_S + (size_t)r * KCB + bx * 128;
            float4 v0, v1;
            v0.x = src[0]; v0.y = src[1]; v0.z = src[2]; v0.w = src[3];
            v1.x = src[4]; v1.y = src[5]; v1.z = src[6]; v1.w = src[7];
            *(float4*)(dst + tx4)      = v0;
            *(float4*)(dst + 64 + tx4) = v1;
        }
    }
}

// ---------------- per-token: m_k = fl(fl(rss+wss_k) - 2*dot_k); argmin (first-index
// ties == reference argmax of -m); KL via log_softmax mimicry ----------------
__global__ void k_reduce(int l) {
    int tid = threadIdx.x;
    int warp = tid >> 5, lane = tid & 31;
    int n = blockIdx.x * 8 + warp;
    const float4* dotr = (const float4*)(g_S + (size_t)n * KCB);
    const float4* wssr = (const float4*)(g_wss + l * KCB);
    float rss = g_rss[n];

    float v[16];
    #pragma unroll
    for (int j = 0; j < 4; j++) {
        int f = lane + j * 32;           // float4 index, k = 4f..4f+3
        float4 d4 = dotr[f];
        float4 w4 = wssr[f];
        v[j*4+0] = __fsub_rn(__fadd_rn(rss, w4.x), 2.0f * d4.x);
        v[j*4+1] = __fsub_rn(__fadd_rn(rss, w4.y), 2.0f * d4.y);
        v[j*4+2] = __fsub_rn(__fadd_rn(rss, w4.z), 2.0f * d4.z);
        v[j*4+3] = __fsub_rn(__fadd_rn(rss, w4.w), 2.0f * d4.w);
    }
    // per-lane argmin in ascending-k order (k = (lane + j*32)*4 + c)
    float best = v[0]; int bidx = lane * 4;
    #pragma unroll
    for (int j = 0; j < 4; j++)
        #pragma unroll
        for (int c = 0; c < 4; c++) {
            int k = (lane + j * 32) * 4 + c;
            float vv = v[j * 4 + c];
            if (vv < best || (vv == best && k < bidx)) { best = vv; bidx = k; }
        }
    #pragma unroll
    for (int o = 16; o; o >>= 1) {
        float ob = __shfl_down_sync(0xffffffffu, best, o);
        int   oi = __shfl_down_sync(0xffffffffu, bidx, o);
        if (ob < best || (ob == best && oi < bidx)) { best = ob; bidx = oi; }
    }
    best = __shfl_sync(0xffffffffu, best, 0);   // min m == -max dist
    bidx = __shfl_sync(0xffffffffu, bidx, 0);

    // log_softmax: shifted_k = fl(dist_k - dmax) = fl(best - v_k)
    float esum = 0.f;
    float sh[16];
    #pragma unroll
    for (int j = 0; j < 16; j++) {
        sh[j] = __fsub_rn(best, v[j]);
        esum += expf(sh[j]);
    }
    #pragma unroll
    for (int o = 16; o; o >>= 1) esum += __shfl_down_sync(0xffffffffu, esum, o);
    esum = __shfl_sync(0xffffffffu, esum, 0);
    float L = logf(esum);
    float psum = 0.f;
    #pragma unroll
    for (int j = 0; j < 16; j++) psum += __fsub_rn(sh[j], L);
    #pragma unroll
    for (int o = 16; o; o >>= 1) psum += __shfl_down_sync(0xffffffffu, psum, o);

    if (lane == 0) {
        float mean = psum * (1.0f / 512.0f);
        float kl = __fsub_rn(-6.238324625039508f, mean);     // -log(512) - mean
        g_kl[n] = __fadd_rn(g_kl[n], __fmul_rn(kl, 0.1f));
        g_idx[n * LLV + l] = bidx;
    }
}

// ---------------- g update: strictly sequential in-order fp32 chain over n ----------
__global__ void k_gchain(const float* __restrict__ W, int l) {
    __shared__ int sidx[2][2048];
    int d = threadIdx.x;
    const float* Wl = W + (size_t)l * KCB * DDIM;
    #pragma unroll
    for (int j = 0; j < 8; j++) sidx[0][d + j * 256] = g_idx[(d + j * 256) * LLV + l];
    __syncthreads();
    float part = 0.f;
    for (int t = 0; t < 8; t++) {
        if (t + 1 < 8) {
            int base = (t + 1) * 2048;
            #pragma unroll
            for (int j = 0; j < 8; j++)
                sidx[(t + 1) & 1][d + j * 256] = g_idx[(base + d + j * 256) * LLV + l];
        }
        const int* s = sidx[t & 1];
        #pragma unroll 16
        for (int j = 0; j < 2048; j++)
            part = __fadd_rn(part, Wl[(size_t)s[j] * DDIM + d]);
        __syncthreads();
    }
    g_g[d] = __fadd_rn(g_g[d], part);
}

// ---------------- q_out (transposed write) + per-token loss ----------------
__global__ void k_final_q(const float* __restrict__ W, float* __restrict__ out,
                          long long o_q) {
    __shared__ int   sidx[32][8];
    __shared__ float sq[32][257];
    int tid = threadIdx.x;
    int tbase = blockIdx.x * 32;
    sidx[tid >> 3][tid & 7] = g_idx[(tbase + (tid >> 3)) * LLV + (tid & 7)];
    __syncthreads();

    int d = tid;
    for (int t = 0; t < 32; t++) {
        float acc = 0.f;
        #pragma unroll
        for (int l = 0; l < LLV; l++)
            acc = __fadd_rn(acc, W[(size_t)(l * KCB + sidx[t][l]) * DDIM + d]);
        sq[t][d] = acc;
    }
    if (tid < 32) {
        int n = tbase + tid;
        float nl = 0.f;
        float un = g_normW[sidx[tid][0]];
        #pragma unroll
        for (int l = 0; l < 7; l++) {
            float lo = g_normW[(l + 1) * KCB + sidx[tid][l + 1]];
            float r  = fmaxf(__fmul_rn(__fdiv_rn(lo, un), 4.0f), 1.0f) - 1.0f;
            nl = __fadd_rn(nl, __fmul_rn(r, r));
            un = lo;
        }
        float nlm = __fdiv_rn(nl, 7.0f);
        g_ltok[n] = __fadd_rn(g_kl[n], __fmul_rn(nlm, 0.1f));
    }
    __syncthreads();
    if (o_q >= 0) {
        int b   = tbase >> 10;
        int hw0 = tbase & 1023;
        float* dst = out + o_q + (size_t)b * (DDIM * 1024);
        for (int it = 0; it < 32; it++) {
            int e = it * 256 + tid;
            int t = e & 31;
            int dd = e >> 5;
            dst[(size_t)dd * 1024 + hw0 + t] = sq[t][dd];
        }
    }
}

// ---------------- per-batch loss mean (in-order chain, /1024 exact) ----------------
__global__ void k_final_loss(float* __restrict__ out, long long o_l) {
    int b = blockIdx.x;
    if (threadIdx.x == 0 && o_l >= 0) {
        float s = 0.f;
        for (int i = 0; i < 1024; i++) s = __fadd_rn(s, g_ltok[b * 1024 + i]);
        out[o_l + b] = s * (1.0f / 1024.0f);
    }
}

// ---------------- indices (as float) + one-hot probs scatter ----------------
__global__ void k_final_scatter(float* __restrict__ out, long long o_i, long long o_p) {
    int gid = blockIdx.x * blockDim.x + threadIdx.x;
    if (gid >= NTOK * LLV) return;
    int iv = g_idx[gid];
    if (o_i >= 0) out[o_i + gid] = (float)iv;
    if (o_p >= 0) out[o_p + (size_t)gid * KCB + iv] = 1.0f;
}

// ---------------- launch ----------------
extern "C" void kernel_launch(void* const* d_in, const int* in_sizes, int n_in,
                              void* d_out, int out_size) {
    const float* z = nullptr;
    const float* w = nullptr;
    for (int i = 0; i < n_in; i++) {
        if (in_sizes[i] == NTOK * DDIM)            z = (const float*)d_in[i];
        else if (in_sizes[i] == LLV * KCB * DDIM)  w = (const float*)d_in[i];
    }
    float* out = (float*)d_out;

    const long long SZ_Q = (long long)BATCH * DDIM * 1024;   // 4194304
    const long long SZ_I = (long long)NTOK * LLV;            // 131072
    const long long SZ_L = BATCH;                            // 16
    const long long SZ_P = (long long)NTOK * LLV * KCB;      // 67108864
    long long o_q = 0, o_i = -1, o_l = -1, o_p = -1;
    long long total = SZ_Q + SZ_I + SZ_L + SZ_P;
    if ((long long)out_size >= total) { o_i = SZ_Q; o_l = o_i + SZ_I; o_p = o_l + SZ_L; }

    cudaMemsetAsync(d_out, 0, (size_t)out_size * sizeof(float), 0);
    k_init<<<64, 256>>>(w);
    for (int l = 0; l < LLV; l++) {
        k_rss<<<2048, 256>>>(z);
        k_gemm<<<dim3(4, 128), 256>>>(z, w + (size_t)l * KCB * DDIM);
        k_reduce<<<2048, 256>>>(l);
        k_gchain<<<1, 256>>>(w, l);
    }
    k_final_q<<<512, 256>>>(w, out, o_q);
    k_final_loss<<<BATCH, 256>>>(out, o_l);
    k_final_scatter<<<512, 256>>>(out, o_i, o_p);
}